// round 6
// baseline (speedup 1.0000x reference)
#include <cuda_runtime.h>
#include <math.h>

#define Bn 4
#define Tn 2048
#define Dn 1024
#define Hn 16
#define HDn 64
#define En 16
#define Rn 64                     // Bn*En active rows
#define QK_SCALE 0.35355339059327373f   // hd^-0.25
#define SM_SCALE 0.125f                 // 1/sqrt(hd)

typedef unsigned long long u64;

// ---------------- scratch (static device globals; no allocation) ----------
__device__ float g_xn[Rn * Dn];
__device__ float g_q[Rn * Dn];
__device__ float g_k[Rn * Dn];
__device__ float g_v[Rn * Dn];
__device__ float g_ai1[Rn * Dn];
__device__ float g_ai2[Rn * Dn];
__device__ float g_ks[3 * 65536];   // LN'd kl per iteration, [it][1024][64]
__device__ float g_vl[3 * 65536];   // vl per iteration
__device__ float g_diffsum;

// ---------------- helpers -------------------------------------------------
__device__ __forceinline__ float warpReduceSum(float v) {
#pragma unroll
    for (int o = 16; o > 0; o >>= 1) v += __shfl_xor_sync(0xffffffffu, v, o);
    return v;
}

__device__ __forceinline__ float blockReduce256(float v, float* sh) {
    __syncthreads();
    v = warpReduceSum(v);
    int wid = threadIdx.x >> 5;
    if ((threadIdx.x & 31) == 0) sh[wid] = v;
    __syncthreads();
    if (threadIdx.x < 32) {
        float t = (threadIdx.x < 8) ? sh[threadIdx.x] : 0.f;
        t = warpReduceSum(t);
        if (threadIdx.x == 0) sh[0] = t;
    }
    __syncthreads();
    return sh[0];
}

// packed fp32x2 FMA (sm_100+): d = a*b + d, lane-wise on a 64-bit pair
__device__ __forceinline__ void ffma2(u64& d, u64 a, u64 b) {
    asm("fma.rn.f32x2 %0, %1, %2, %0;" : "+l"(d) : "l"(a), "l"(b));
}

__device__ __forceinline__ unsigned smem_u32p(const void* p) {
    return (unsigned)__cvta_generic_to_shared(p);
}
__device__ __forceinline__ void cp16(unsigned dst, const void* src) {
    asm volatile("cp.async.cg.shared.global [%0], [%1], 16;" :: "r"(dst), "l"(src));
}
__device__ __forceinline__ void cp8(unsigned dst, const void* src) {
    asm volatile("cp.async.ca.shared.global [%0], [%1], 8;" :: "r"(dst), "l"(src));
}
__device__ __forceinline__ void cp_commit() {
    asm volatile("cp.async.commit_group;");
}
__device__ __forceinline__ void cp_wait0() {
    asm volatile("cp.async.wait_group 0;");
}
// vector float atomic add (sm_90+)
__device__ __forceinline__ void red4(float* p, float a, float b, float c, float d) {
    asm volatile("red.global.add.v4.f32 [%0], {%1,%2,%3,%4};"
                 :: "l"(p), "f"(a), "f"(b), "f"(c), "f"(d) : "memory");
}

// ======================= K1a: LN(64 rows) + accumulator inits =============
__global__ __launch_bounds__(256) void k_ln(
    const float* __restrict__ x, const float* __restrict__ lna,
    const float* __restrict__ bq, const float* __restrict__ bv) {
    if (blockIdx.x < Rn) {
        __shared__ float sh[8];
        if (blockIdx.x == 0 && threadIdx.x == 0) g_diffsum = 0.f;
        int r = blockIdx.x;
        int b = r >> 4, t = r & 15;
        const float* xr = x + ((size_t)(b * Tn + t)) * Dn;
        int tid = threadIdx.x;
        float v[4];
        float s = 0.f;
#pragma unroll
        for (int i = 0; i < 4; i++) { v[i] = xr[tid + i * 256]; s += v[i]; }
        s = blockReduce256(s, sh);
        float mean = s * (1.f / 1024.f);
        float sq = 0.f;
#pragma unroll
        for (int i = 0; i < 4; i++) { float d = v[i] - mean; sq += d * d; }
        sq = blockReduce256(sq, sh);
        float inv = rsqrtf(sq * (1.f / 1024.f) + 1e-5f);
#pragma unroll
        for (int i = 0; i < 4; i++) {
            int j = tid + i * 256;
            g_xn[r * Dn + j] = (v[i] - mean) * inv * lna[j];
        }
    } else {
        // init accumulators with biases (k-split GEMMs red.add onto these)
        int r = blockIdx.x - Rn;
        int tid = threadIdx.x;
#pragma unroll
        for (int i = 0; i < 4; i++) {
            int j = tid + i * 256;
            g_q[r * Dn + j] = bq[j] * QK_SCALE;
            g_k[r * Dn + j] = 0.f;
            g_v[r * Dn + j] = bv[j];
        }
    }
}

// ======================= K1b: bo fill of whole output (side stream) =======
__global__ __launch_bounds__(256) void k_fill(
    const float* __restrict__ bo, float* __restrict__ out) {
    const float4* bo4 = (const float4*)bo;
    float4* o4 = (float4*)out;
    size_t total = (size_t)Bn * Tn * Dn / 4;           // 2,097,152
    size_t start = (size_t)blockIdx.x * 256 + threadIdx.x;
    size_t stride = (size_t)gridDim.x * 256;           // multiple of 256
    float4 v = bo4[start & 255];
    for (size_t i = start; i < total; i += stride) o4[i] = v;
}

// ======================= 64x128 FFMA2 GEMM tile core ======================
#define TK 64

__device__ __forceinline__ void stage_tile(
    const float* __restrict__ A, const float* __restrict__ W,
    int j0, int kb, float* sA, float* sW) {
    int tid = threadIdx.x;
#pragma unroll
    for (int c = tid; c < 64 * TK / 2; c += 128) {
        int r = c >> 5;
        int kf = (c & 31) * 2;
        int rg = r >> 3;
        int swz = ((rg & 3) * 8) | ((rg >> 2) * 2);
        cp8(smem_u32p(&sA[r * TK + (kf ^ swz)]),
            &A[(size_t)r * Dn + kb + kf]);
    }
#pragma unroll
    for (int c = tid; c < 128 * TK / 4; c += 128) {
        int r = c >> 4;
        int kf = (c & 15) * 4;
        cp16(smem_u32p(&sW[r * TK + kf]),
             &W[(size_t)(j0 + r) * Dn + kb + kf]);
    }
    cp_commit();
}

__device__ __forceinline__ void compute_tile(
    const float* sA, const float* sW, u64* acc, int rg, int cg) {
    int swz = ((rg & 3) * 8) | ((rg >> 2) * 2);
    const float* aBase = sA + rg * 8 * TK;
    const float* wBase = sW + cg * 8 * TK;
#pragma unroll 4
    for (int kk = 0; kk < TK; kk += 2) {
        int ka = kk ^ swz;
        u64 av[8], wv[8];
#pragma unroll
        for (int i = 0; i < 8; i++)
            av[i] = *(const u64*)&aBase[i * TK + ka];
#pragma unroll
        for (int j = 0; j < 8; j++)
            wv[j] = *(const u64*)&wBase[j * TK + kk];
#pragma unroll
        for (int i = 0; i < 8; i++)
#pragma unroll
            for (int j = 0; j < 8; j++) ffma2(acc[i * 8 + j], av[i], wv[j]);
    }
}
#define GEMM_SMEM ((64 + 128) * TK * 4)   // 49152 bytes

// ======================= K2: q,k,v GEMMs (k-split 16, red.v4) =============
__global__ __launch_bounds__(128) void k_qkv(
    const float* __restrict__ Wq, const float* __restrict__ Wk,
    const float* __restrict__ Wv) {
    extern __shared__ float sh[];
    float* sA = sh;
    float* sW = sh + 64 * TK;
    int m = blockIdx.z;
    const float* W = (m == 0) ? Wq : (m == 1) ? Wk : Wv;
    float* dst = (m == 0) ? g_q : (m == 1) ? g_k : g_v;
    float scale = (m == 2) ? 1.0f : QK_SCALE;
    int j0 = blockIdx.x * 128;
    int kb = blockIdx.y * TK;
    u64 acc[64] = {};
    stage_tile(g_xn, W, j0, kb, sA, sW);
    cp_wait0();
    __syncthreads();
    int tid = threadIdx.x, rg = tid & 7, cg = tid >> 3;
    compute_tile(sA, sW, acc, rg, cg);
    int c0 = j0 + cg * 8;
#pragma unroll
    for (int i = 0; i < 8; i++) {
        int row = rg * 8 + i;
        float v[8];
#pragma unroll
        for (int j = 0; j < 8; j++) {
            float2 f = *(float2*)&acc[i * 8 + j];
            v[j] = (f.x + f.y) * scale;
        }
        float* p = &dst[(size_t)row * Dn + c0];
        red4(p, v[0], v[1], v[2], v[3]);
        red4(p + 4, v[4], v[5], v[6], v[7]);
    }
}

// ======================= K3a: precompute kl/vl recurrence (row-parallel) ==
// kl_{it} = kcur @ Wlk^T + blk ; ks_it = LN(kl_it)*lnd ; vl analogous.
// g_k/g_v viewed as [1024][64]; each block owns 8 consecutive rows.
__global__ __launch_bounds__(256, 1) void k_kv(
    const float* __restrict__ Wlk, const float* __restrict__ blk,
    const float* __restrict__ Wlv, const float* __restrict__ blv,
    const float* __restrict__ lnd) {
    __shared__ float kcur[8 * 64];
    __shared__ float vcur[8 * 64];
    __shared__ float wk[64 * 66];
    __shared__ float wv[64 * 66];
    int tid = threadIdx.x;
    int r0 = blockIdx.x * 8;
    for (int idx = tid; idx < 4096; idx += 256) {
        int j = idx >> 6, d = idx & 63;
        wk[j * 66 + d] = Wlk[idx];
        wv[j * 66 + d] = Wlv[idx];
    }
    for (int i = tid; i < 512; i += 256) {
        kcur[i] = g_k[(size_t)r0 * 64 + i];
        vcur[i] = g_v[(size_t)r0 * 64 + i];
    }
    int m = tid >> 7;            // 0 = k, 1 = v
    int u = tid & 127;
    int ra = u & 3;              // rows ra, ra+4
    int c2 = u >> 2;             // cols 2c2, 2c2+1
    const float* in = m ? vcur : kcur;
    const float* w  = m ? wv : wk;
    const float* bl = m ? blv : blk;
    float bl0 = bl[2 * c2], bl1 = bl[2 * c2 + 1];
    int l4 = tid & 15;
    float4 lw4 = make_float4(0.f, 0.f, 0.f, 0.f);
    if (tid < 128) lw4 = *(const float4*)&lnd[l4 * 4];
    __syncthreads();

    for (int it = 0; it < 3; it++) {
        u64 a00 = 0, a01 = 0, a10 = 0, a11 = 0;
#pragma unroll 8
        for (int dd = 0; dd < 32; dd++) {
            int d = (2 * (dd + tid)) & 62;
            u64 i0 = *(const u64*)&in[ra * 64 + d];
            u64 i1 = *(const u64*)&in[(ra + 4) * 64 + d];
            u64 w0 = *(const u64*)&w[(2 * c2) * 66 + d];
            u64 w1 = *(const u64*)&w[(2 * c2 + 1) * 66 + d];
            ffma2(a00, i0, w0); ffma2(a01, i0, w1);
            ffma2(a10, i1, w0); ffma2(a11, i1, w1);
        }
        __syncthreads();           // all reads of kcur/vcur done
        float2 f;
        f = *(float2*)&a00; float o00 = f.x + f.y + bl0;
        f = *(float2*)&a01; float o01 = f.x + f.y + bl1;
        f = *(float2*)&a10; float o10 = f.x + f.y + bl0;
        f = *(float2*)&a11; float o11 = f.x + f.y + bl1;
        float* dst = m ? vcur : kcur;
        dst[ra * 64 + 2 * c2] = o00;     dst[ra * 64 + 2 * c2 + 1] = o01;
        dst[(ra + 4) * 64 + 2 * c2] = o10; dst[(ra + 4) * 64 + 2 * c2 + 1] = o11;
        if (m) {                   // vl straight to global
            size_t g = (size_t)it * 65536 + (size_t)(r0 + ra) * 64 + 2 * c2;
            *(float2*)&g_vl[g] = make_float2(o00, o01);
            *(float2*)&g_vl[g + 256] = make_float2(o10, o11);
        }
        __syncthreads();           // writes visible
        // LN of kl rows (threads 0..127, one row per half-warp) -> g_ks
        if (tid < 128) {
            int rr = tid >> 4;
            float4 v = *(float4*)&kcur[rr * 64 + l4 * 4];
            float s = v.x + v.y + v.z + v.w;
#pragma unroll
            for (int o = 8; o > 0; o >>= 1) s += __shfl_xor_sync(0xffffffffu, s, o, 16);
            float mean = s * (1.f / 64.f);
            float dx = v.x - mean, dy = v.y - mean, dz = v.z - mean, dw = v.w - mean;
            float sq = dx * dx + dy * dy + dz * dz + dw * dw;
#pragma unroll
            for (int o = 8; o > 0; o >>= 1) sq += __shfl_xor_sync(0xffffffffu, sq, o, 16);
            float inv = rsqrtf(sq * (1.f / 64.f) + 1e-5f);
            float4 r4 = make_float4(dx * inv * lw4.x, dy * inv * lw4.y,
                                    dz * inv * lw4.z, dw * inv * lw4.w);
            *(float4*)&g_ks[(size_t)it * 65536 + (size_t)(r0 + rr) * 64 + l4 * 4] = r4;
        }
        // no extra sync: next gemm only READS kcur/vcur; LN only reads too.
    }
}

// ======================= K3b: slim per-head attention loop ================
__global__ __launch_bounds__(256, 1) void k_iter(
    const float* __restrict__ Wlq, const float* __restrict__ blq,
    const float* __restrict__ lnc, const float* __restrict__ temp_p) {
    extern __shared__ float sm[];
    float* wq   = sm;                 // 64*66
    float* qcur = wq + 64 * 66;       // 1024
    float* qlb  = qcur + 1024;        // 1024
    float* ks   = qlb + 1024;         // 3*1024
    float* vl   = ks + 3072;          // 3*1024
    float* p    = vl + 3072;          // 256
    float* red  = p + 256;            // 32

    int tid = threadIdx.x;
    int bb = blockIdx.x >> 4, h = blockIdx.x & 15;

    for (int idx = tid; idx < 4096; idx += 256) {
        int j = idx >> 6, d = idx & 63;
        wq[j * 66 + d] = Wlq[idx];
    }
    for (int i = tid; i < 1024; i += 256) {
        int e = i >> 6, d = i & 63;
        qcur[i] = g_q[(size_t)((bb * 16 + e) * 16 + h) * 64 + d];
    }
    for (int i = tid; i < 3072; i += 256) {
        int itc = i >> 10, r = i & 1023;
        int e = r >> 6, d = r & 63;
        size_t off = (size_t)itc * 65536 + (size_t)((bb * 16 + e) * 16 + h) * 64 + d;
        ks[i] = g_ks[off];
        vl[i] = g_vl[off];
    }
    int ra = tid & 7;            // rows ra, ra+8
    int c2 = tid >> 3;           // cols 2c2, 2c2+1
    int e_sm = tid >> 4, f_sm = tid & 15;
    int l4 = tid & 15;
    float blq0 = blq[2 * c2], blq1 = blq[2 * c2 + 1];
    float4 lw4 = *(const float4*)&lnc[l4 * 4];
    float temp0 = temp_p[0];
    float ap0 = 0.f, ap1 = 0.f, ap2 = 0.f, ap3 = 0.f;
    __syncthreads();

    for (int it = 0; it < 3; it++) {
        // ---- ql = qcur @ Wlq^T + blq (all 256 threads, 2x2 tiles) ----
        u64 a00 = 0, a01 = 0, a10 = 0, a11 = 0;
#pragma unroll 8
        for (int dd = 0; dd < 32; dd++) {
            int d = (2 * (dd + tid)) & 62;
            u64 i0 = *(const u64*)&qcur[ra * 64 + d];
            u64 i1 = *(const u64*)&qcur[(ra + 8) * 64 + d];
            u64 w0 = *(const u64*)&wq[(2 * c2) * 66 + d];
            u64 w1 = *(const u64*)&wq[(2 * c2 + 1) * 66 + d];
            ffma2(a00, i0, w0); ffma2(a01, i0, w1);
            ffma2(a10, i1, w0); ffma2(a11, i1, w1);
        }
        __syncthreads();
        {
            float2 f;
            f = *(float2*)&a00; qlb[ra * 64 + 2 * c2]           = f.x + f.y + blq0;
            f = *(float2*)&a01; qlb[ra * 64 + 2 * c2 + 1]       = f.x + f.y + blq1;
            f = *(float2*)&a10; qlb[(ra + 8) * 64 + 2 * c2]     = f.x + f.y + blq0;
            f = *(float2*)&a11; qlb[(ra + 8) * 64 + 2 * c2 + 1] = f.x + f.y + blq1;
        }
        __syncthreads();
        // ---- LN(ql) * tsc * SM_SCALE (one row per half-warp) ----
        float t_it = temp0 + 0.005f * (float)it;
        float tsc = ((t_it != 1.0f) && (t_it > 0.f)) ? rsqrtf(t_it) : 1.0f;
        float sc = tsc * SM_SCALE;
        {
            int rr = tid >> 4;
            float4 v = *(float4*)&qlb[rr * 64 + l4 * 4];
            float s = v.x + v.y + v.z + v.w;
#pragma unroll
            for (int o = 8; o > 0; o >>= 1) s += __shfl_xor_sync(0xffffffffu, s, o, 16);
            float mean = s * (1.f / 64.f);
            float dx = v.x - mean, dy = v.y - mean, dz = v.z - mean, dw = v.w - mean;
            float sq = dx * dx + dy * dy + dz * dz + dw * dw;
#pragma unroll
            for (int o = 8; o > 0; o >>= 1) sq += __shfl_xor_sync(0xffffffffu, sq, o, 16);
            float inv = rsqrtf(sq * (1.f / 64.f) + 1e-5f) * sc;
            float4 r4 = make_float4(dx * inv * lw4.x, dy * inv * lw4.y,
                                    dz * inv * lw4.z, dw * inv * lw4.w);
            *(float4*)&qlb[rr * 64 + l4 * 4] = r4;
        }
        __syncthreads();
        // ---- logits (one per thread) + parallel softmax ----
        {
            const float* kst = ks + it * 1024;
            u64 acc0 = 0, acc1 = 0;
#pragma unroll 8
            for (int dd = 0; dd < 32; dd += 2) {
                int d0 = (2 * (dd + tid)) & 62;
                int d1 = (2 * (dd + 1 + tid)) & 62;
                ffma2(acc0, *(const u64*)&qlb[e_sm * 64 + d0],
                            *(const u64*)&kst[f_sm * 64 + d0]);
                ffma2(acc1, *(const u64*)&qlb[e_sm * 64 + d1],
                            *(const u64*)&kst[f_sm * 64 + d1]);
            }
            float2 f0 = *(float2*)&acc0, f1 = *(float2*)&acc1;
            float lg = f0.x + f0.y + f1.x + f1.y;
            float mx = lg;
#pragma unroll
            for (int o = 8; o > 0; o >>= 1)
                mx = fmaxf(mx, __shfl_xor_sync(0xffffffffu, mx, o, 16));
            float ex = __expf(lg - mx);
            float s = ex;
#pragma unroll
            for (int o = 8; o > 0; o >>= 1)
                s += __shfl_xor_sync(0xffffffffu, s, o, 16);
            p[tid] = __fdividef(ex, s);
        }
        __syncthreads();
        // ---- ai = softmax @ vl ; bookkeeping ----
        {
            const float* vlt = vl + it * 1024;
            float b00 = 0, b01 = 0, b10 = 0, b11 = 0;
#pragma unroll
            for (int f = 0; f < 16; f++) {
                float p0 = p[ra * 16 + f];
                float p1 = p[(ra + 8) * 16 + f];
                float2 vv = *(const float2*)&vlt[f * 64 + 2 * c2];
                b00 = fmaf(p0, vv.x, b00); b01 = fmaf(p0, vv.y, b01);
                b10 = fmaf(p1, vv.x, b10); b11 = fmaf(p1, vv.y, b11);
            }
            if (it == 0) { ap0 = b00; ap1 = b01; ap2 = b10; ap3 = b11; }
            if (it >= 1) {
                float* dst = (it == 1) ? g_ai1 : g_ai2;
                size_t g0 = (size_t)((bb * 16 + ra) * 16 + h) * 64 + 2 * c2;
                size_t g1 = (size_t)((bb * 16 + ra + 8) * 16 + h) * 64 + 2 * c2;
                *(float2*)&dst[g0] = make_float2(b00, b01);
                *(float2*)&dst[g1] = make_float2(b10, b11);
            }
            qcur[ra * 64 + 2 * c2]           += b00;
            qcur[ra * 64 + 2 * c2 + 1]       += b01;
            qcur[(ra + 8) * 64 + 2 * c2]     += b10;
            qcur[(ra + 8) * 64 + 2 * c2 + 1] += b11;
            if (it == 1) {
                float ds = fabsf(b00 - ap0) + fabsf(b01 - ap1) +
                           fabsf(b10 - ap2) + fabsf(b11 - ap3);
                float tot = blockReduce256(ds, red);
                if (tid == 0) atomicAdd(&g_diffsum, tot);
            }
        }
        __syncthreads();
    }
}
#define KITER_SMEM ((64 * 66 + 1024 + 1024 + 3072 + 3072 + 256 + 32) * 4)

// ======================= K4: select ai, Wo proj, red.v4 into out ==========
__global__ __launch_bounds__(128) void k_out(
    const float* __restrict__ Wo, const float* __restrict__ thrp,
    const float* __restrict__ facp, float* __restrict__ out) {
    extern __shared__ float sh[];
    float* sA = sh;
    float* sW = sh + 64 * TK;
    float diff1 = g_diffsum * (1.0f / 8388608.0f);  // mean over B*H*T*hd
    const float* A = (diff1 < thrp[0] + facp[0] * diff1) ? g_ai1 : g_ai2;
    int j0 = blockIdx.x * 128;
    int kb = blockIdx.y * TK;
    u64 acc[64] = {};
    stage_tile(A, Wo, j0, kb, sA, sW);
    cp_wait0();
    __syncthreads();
    int tid = threadIdx.x, rg = tid & 7, cg = tid >> 3;
    compute_tile(sA, sW, acc, rg, cg);
    int c0 = j0 + cg * 8;
#pragma unroll
    for (int i = 0; i < 8; i++) {
        int row = rg * 8 + i;
        int b = row >> 4, t = row & 15;
        float v[8];
#pragma unroll
        for (int j = 0; j < 8; j++) {
            float2 f = *(float2*)&acc[i * 8 + j];
            v[j] = f.x + f.y;
        }
        float* p = &out[((size_t)(b * Tn + t)) * Dn + c0];
        red4(p, v[0], v[1], v[2], v[3]);
        red4(p + 4, v[4], v[5], v[6], v[7]);
    }
}

// ======================= launch ===========================================
extern "C" void kernel_launch(void* const* d_in, const int* in_sizes, int n_in,
                              void* d_out, int out_size) {
    (void)in_sizes; (void)n_in; (void)out_size;
    const float* x    = (const float*)d_in[0];
    const float* Wq   = (const float*)d_in[1];
    const float* bq   = (const float*)d_in[2];
    const float* Wk   = (const float*)d_in[3];
    const float* Wv   = (const float*)d_in[4];
    const float* bv   = (const float*)d_in[5];
    const float* Wo   = (const float*)d_in[6];
    const float* bo   = (const float*)d_in[7];
    const float* lna  = (const float*)d_in[8];
    const float* lnc  = (const float*)d_in[9];
    const float* lnd  = (const float*)d_in[10];
    const float* Wlq  = (const float*)d_in[11];
    const float* blq  = (const float*)d_in[12];
    const float* Wlk  = (const float*)d_in[13];
    const float* blk  = (const float*)d_in[14];
    const float* Wlv  = (const float*)d_in[15];
    const float* blv  = (const float*)d_in[16];
    const float* temp = (const float*)d_in[17];
    const float* thr  = (const float*)d_in[18];
    const float* fac  = (const float*)d_in[19];
    float* out = (float*)d_out;

    static cudaStream_t s2 = nullptr;
    static cudaEvent_t evF = nullptr, evJ = nullptr;
    static bool attrs_set = false;
    if (s2 == nullptr) {
        cudaStreamCreateWithFlags(&s2, cudaStreamNonBlocking);
        cudaEventCreateWithFlags(&evF, cudaEventDisableTiming);
        cudaEventCreateWithFlags(&evJ, cudaEventDisableTiming);
    }
    if (!attrs_set) {
        cudaFuncSetAttribute(k_qkv,  cudaFuncAttributeMaxDynamicSharedMemorySize, GEMM_SMEM);
        cudaFuncSetAttribute(k_out,  cudaFuncAttributeMaxDynamicSharedMemorySize, GEMM_SMEM);
        cudaFuncSetAttribute(k_iter, cudaFuncAttributeMaxDynamicSharedMemorySize, KITER_SMEM);
        attrs_set = true;
    }

    // fork: bo-fill runs concurrently on s2
    cudaEventRecord(evF, 0);
    cudaStreamWaitEvent(s2, evF, 0);
    k_fill<<<1024, 256, 0, s2>>>(bo, out);

    // main chain on stream 0
    k_ln<<<128, 256>>>(x, lna, bq, bv);
    k_qkv<<<dim3(8, 16, 3), 128, GEMM_SMEM>>>(Wq, Wk, Wv);
    k_kv<<<128, 256>>>(Wlk, blk, Wlv, blv, lnd);
    k_iter<<<64, 256, KITER_SMEM>>>(Wlq, blq, lnc, temp);

    // join fill before final projection (which red.adds into out)
    cudaEventRecord(evJ, s2);
    cudaStreamWaitEvent(0, evJ, 0);
    k_out<<<dim3(8, 16), 128, GEMM_SMEM>>>(Wo, thr, fac, out);
}

// round 7
// speedup vs baseline: 1.1216x; 1.1216x over previous
#include <cuda_runtime.h>
#include <math.h>

#define Bn 4
#define Tn 2048
#define Dn 1024
#define Hn 16
#define HDn 64
#define En 16
#define Rn 64                     // Bn*En active rows
#define QK_SCALE 0.35355339059327373f   // hd^-0.25
#define SM_SCALE 0.125f                 // 1/sqrt(hd)

typedef unsigned long long u64;

// ---------------- scratch (static device globals; no allocation) ----------
__device__ float g_xn[Rn * Dn];
__device__ float g_q[Rn * Dn];
__device__ float g_k[Rn * Dn];
__device__ float g_v[Rn * Dn];
__device__ float g_ai1[Rn * Dn];
__device__ float g_ai2[Rn * Dn];
__device__ float g_ks[3 * 65536];   // LN'd kl per iteration, [it][1024][64]
__device__ float g_vl[3 * 65536];   // vl per iteration
__device__ int   g_done[3];         // producer completion counters (target 64)
__device__ float g_diffsum;

// ---------------- helpers -------------------------------------------------
__device__ __forceinline__ float warpReduceSum(float v) {
#pragma unroll
    for (int o = 16; o > 0; o >>= 1) v += __shfl_xor_sync(0xffffffffu, v, o);
    return v;
}

__device__ __forceinline__ float blockReduce256(float v, float* sh) {
    __syncthreads();
    v = warpReduceSum(v);
    int wid = threadIdx.x >> 5;
    if ((threadIdx.x & 31) == 0) sh[wid] = v;
    __syncthreads();
    if (threadIdx.x < 32) {
        float t = (threadIdx.x < 8) ? sh[threadIdx.x] : 0.f;
        t = warpReduceSum(t);
        if (threadIdx.x == 0) sh[0] = t;
    }
    __syncthreads();
    return sh[0];
}

// packed fp32x2 FMA (sm_100+): d = a*b + d, lane-wise on a 64-bit pair
__device__ __forceinline__ void ffma2(u64& d, u64 a, u64 b) {
    asm("fma.rn.f32x2 %0, %1, %2, %0;" : "+l"(d) : "l"(a), "l"(b));
}

__device__ __forceinline__ unsigned smem_u32p(const void* p) {
    return (unsigned)__cvta_generic_to_shared(p);
}
__device__ __forceinline__ void cp16(unsigned dst, const void* src) {
    asm volatile("cp.async.cg.shared.global [%0], [%1], 16;" :: "r"(dst), "l"(src));
}
__device__ __forceinline__ void cp8(unsigned dst, const void* src) {
    asm volatile("cp.async.ca.shared.global [%0], [%1], 8;" :: "r"(dst), "l"(src));
}
__device__ __forceinline__ void cp_commit() {
    asm volatile("cp.async.commit_group;");
}
__device__ __forceinline__ void cp_wait0() {
    asm volatile("cp.async.wait_group 0;");
}
// vector float atomic add (sm_90+)
__device__ __forceinline__ void red4(float* p, float a, float b, float c, float d) {
    asm volatile("red.global.add.v4.f32 [%0], {%1,%2,%3,%4};"
                 :: "l"(p), "f"(a), "f"(b), "f"(c), "f"(d) : "memory");
}
__device__ __forceinline__ int ld_acquire(const int* p) {
    int v;
    asm volatile("ld.acquire.gpu.global.b32 %0, [%1];" : "=r"(v) : "l"(p));
    return v;
}

// ======================= K1a: LN(64 rows) + accumulator inits =============
__global__ __launch_bounds__(256) void k_ln(
    const float* __restrict__ x, const float* __restrict__ lna,
    const float* __restrict__ bq, const float* __restrict__ bv) {
    if (blockIdx.x < Rn) {
        __shared__ float sh[8];
        if (blockIdx.x == 0 && threadIdx.x == 0) g_diffsum = 0.f;
        if (blockIdx.x == 0 && threadIdx.x < 3) g_done[threadIdx.x] = 0;
        int r = blockIdx.x;
        int b = r >> 4, t = r & 15;
        const float* xr = x + ((size_t)(b * Tn + t)) * Dn;
        int tid = threadIdx.x;
        float v[4];
        float s = 0.f;
#pragma unroll
        for (int i = 0; i < 4; i++) { v[i] = xr[tid + i * 256]; s += v[i]; }
        s = blockReduce256(s, sh);
        float mean = s * (1.f / 1024.f);
        float sq = 0.f;
#pragma unroll
        for (int i = 0; i < 4; i++) { float d = v[i] - mean; sq += d * d; }
        sq = blockReduce256(sq, sh);
        float inv = rsqrtf(sq * (1.f / 1024.f) + 1e-5f);
#pragma unroll
        for (int i = 0; i < 4; i++) {
            int j = tid + i * 256;
            g_xn[r * Dn + j] = (v[i] - mean) * inv * lna[j];
        }
    } else {
        int r = blockIdx.x - Rn;
        int tid = threadIdx.x;
#pragma unroll
        for (int i = 0; i < 4; i++) {
            int j = tid + i * 256;
            g_q[r * Dn + j] = bq[j] * QK_SCALE;
            g_k[r * Dn + j] = 0.f;
            g_v[r * Dn + j] = bv[j];
        }
    }
}

// ======================= K1b: bo fill of whole output (side stream) =======
__global__ __launch_bounds__(256) void k_fill(
    const float* __restrict__ bo, float* __restrict__ out) {
    const float4* bo4 = (const float4*)bo;
    float4* o4 = (float4*)out;
    size_t total = (size_t)Bn * Tn * Dn / 4;
    size_t start = (size_t)blockIdx.x * 256 + threadIdx.x;
    size_t stride = (size_t)gridDim.x * 256;
    float4 v = bo4[start & 255];
    for (size_t i = start; i < total; i += stride) o4[i] = v;
}

// ======================= 64x128 FFMA2 GEMM tile core ======================
#define TK 64

__device__ __forceinline__ void stage_tile(
    const float* __restrict__ A, const float* __restrict__ W,
    int j0, int kb, float* sA, float* sW) {
    int tid = threadIdx.x;
#pragma unroll
    for (int c = tid; c < 64 * TK / 2; c += 128) {
        int r = c >> 5;
        int kf = (c & 31) * 2;
        int rg = r >> 3;
        int swz = ((rg & 3) * 8) | ((rg >> 2) * 2);
        cp8(smem_u32p(&sA[r * TK + (kf ^ swz)]),
            &A[(size_t)r * Dn + kb + kf]);
    }
#pragma unroll
    for (int c = tid; c < 128 * TK / 4; c += 128) {
        int r = c >> 4;
        int kf = (c & 15) * 4;
        cp16(smem_u32p(&sW[r * TK + kf]),
             &W[(size_t)(j0 + r) * Dn + kb + kf]);
    }
    cp_commit();
}

__device__ __forceinline__ void compute_tile(
    const float* sA, const float* sW, u64* acc, int rg, int cg) {
    int swz = ((rg & 3) * 8) | ((rg >> 2) * 2);
    const float* aBase = sA + rg * 8 * TK;
    const float* wBase = sW + cg * 8 * TK;
#pragma unroll 4
    for (int kk = 0; kk < TK; kk += 2) {
        int ka = kk ^ swz;
        u64 av[8], wv[8];
#pragma unroll
        for (int i = 0; i < 8; i++)
            av[i] = *(const u64*)&aBase[i * TK + ka];
#pragma unroll
        for (int j = 0; j < 8; j++)
            wv[j] = *(const u64*)&wBase[j * TK + kk];
#pragma unroll
        for (int i = 0; i < 8; i++)
#pragma unroll
            for (int j = 0; j < 8; j++) ffma2(acc[i * 8 + j], av[i], wv[j]);
    }
}
#define GEMM_SMEM ((64 + 128) * TK * 4)   // 49152 bytes

// ======================= K2: q,k,v GEMMs (k-split 16, red.v4) =============
__global__ __launch_bounds__(128) void k_qkv(
    const float* __restrict__ Wq, const float* __restrict__ Wk,
    const float* __restrict__ Wv) {
    extern __shared__ float sh[];
    float* sA = sh;
    float* sW = sh + 64 * TK;
    int m = blockIdx.z;
    const float* W = (m == 0) ? Wq : (m == 1) ? Wk : Wv;
    float* dst = (m == 0) ? g_q : (m == 1) ? g_k : g_v;
    float scale = (m == 2) ? 1.0f : QK_SCALE;
    int j0 = blockIdx.x * 128;
    int kb = blockIdx.y * TK;
    u64 acc[64] = {};
    stage_tile(g_xn, W, j0, kb, sA, sW);
    cp_wait0();
    __syncthreads();
    int tid = threadIdx.x, rg = tid & 7, cg = tid >> 3;
    compute_tile(sA, sW, acc, rg, cg);
    int c0 = j0 + cg * 8;
#pragma unroll
    for (int i = 0; i < 8; i++) {
        int row = rg * 8 + i;
        float v[8];
#pragma unroll
        for (int j = 0; j < 8; j++) {
            float2 f = *(float2*)&acc[i * 8 + j];
            v[j] = (f.x + f.y) * scale;
        }
        float* p = &dst[(size_t)row * Dn + c0];
        red4(p, v[0], v[1], v[2], v[3]);
        red4(p + 4, v[4], v[5], v[6], v[7]);
    }
}

// ======================= K3: fused producer/consumer middle kernel ========
// Blocks 0..63   : consumer — per-(b,h) q-attention chain.
// Blocks 64..95  : K-producer — 32 rows of kl recurrence + LN -> g_ks.
// Blocks 96..127 : V-producer — 32 rows of vl recurrence -> g_vl.
// Producers bump g_done[it] (target 64) with release semantics.
__global__ __launch_bounds__(256, 1) void k_mid(
    const float* __restrict__ Wlq, const float* __restrict__ blq,
    const float* __restrict__ Wlk, const float* __restrict__ blk,
    const float* __restrict__ Wlv, const float* __restrict__ blv,
    const float* __restrict__ lnc, const float* __restrict__ lnd,
    const float* __restrict__ temp_p) {
    extern __shared__ float sm[];
    int tid = threadIdx.x;
    int bx = blockIdx.x;

    if (bx >= 64) {
        // =================== producer ===================
        bool isK = (bx < 96);
        int r0 = (isK ? (bx - 64) : (bx - 96)) * 32;
        float* w   = sm;              // 64*66
        float* cur = w + 64 * 66;     // 32*64
        const float* Wm = isK ? Wlk : Wlv;
        const float* bl = isK ? blk : blv;
        const float* gsrc = isK ? g_k : g_v;
        for (int idx = tid; idx < 4096; idx += 256) {
            int j = idx >> 6, d = idx & 63;
            w[j * 66 + d] = Wm[idx];
        }
        for (int i = tid; i < 2048; i += 256)
            cur[i] = gsrc[(size_t)r0 * 64 + i];
        int ra = tid & 7;             // rows ra+8*i (i=0..3)
        int c2 = tid >> 3;            // cols 2c2, 2c2+1
        float bl0 = bl[2 * c2], bl1 = bl[2 * c2 + 1];
        int l4 = tid & 15;
        float4 lw4 = *(const float4*)&lnd[l4 * 4];
        __syncthreads();

        for (int it = 0; it < 3; it++) {
            u64 acc0[4] = {}, acc1[4] = {};
#pragma unroll 8
            for (int dd = 0; dd < 32; dd++) {
                int d = (2 * (dd + tid)) & 62;
                u64 w0 = *(const u64*)&w[(2 * c2) * 66 + d];
                u64 w1 = *(const u64*)&w[(2 * c2 + 1) * 66 + d];
#pragma unroll
                for (int i = 0; i < 4; i++) {
                    u64 iv = *(const u64*)&cur[(ra + 8 * i) * 64 + d];
                    ffma2(acc0[i], iv, w0);
                    ffma2(acc1[i], iv, w1);
                }
            }
            __syncthreads();          // reads of cur done
#pragma unroll
            for (int i = 0; i < 4; i++) {
                int row = ra + 8 * i;
                float2 f0 = *(float2*)&acc0[i];
                float2 f1 = *(float2*)&acc1[i];
                float o0 = f0.x + f0.y + bl0;
                float o1 = f1.x + f1.y + bl1;
                cur[row * 64 + 2 * c2] = o0;
                cur[row * 64 + 2 * c2 + 1] = o1;
                if (!isK) {
                    *(float2*)&g_vl[(size_t)it * 65536 +
                                    (size_t)(r0 + row) * 64 + 2 * c2] =
                        make_float2(o0, o1);
                }
            }
            __syncthreads();          // writes visible in smem
            if (isK) {                // LN rows -> g_ks (2 rows per half-warp)
                int rr = tid >> 4;
#pragma unroll
                for (int rb = 0; rb < 2; rb++) {
                    int row = rr + rb * 16;
                    float4 v = *(float4*)&cur[row * 64 + l4 * 4];
                    float s = v.x + v.y + v.z + v.w;
#pragma unroll
                    for (int o = 8; o > 0; o >>= 1)
                        s += __shfl_xor_sync(0xffffffffu, s, o, 16);
                    float mean = s * (1.f / 64.f);
                    float dx = v.x - mean, dy = v.y - mean;
                    float dz = v.z - mean, dw = v.w - mean;
                    float sq = dx * dx + dy * dy + dz * dz + dw * dw;
#pragma unroll
                    for (int o = 8; o > 0; o >>= 1)
                        sq += __shfl_xor_sync(0xffffffffu, sq, o, 16);
                    float inv = rsqrtf(sq * (1.f / 64.f) + 1e-5f);
                    *(float4*)&g_ks[(size_t)it * 65536 +
                                    (size_t)(r0 + row) * 64 + l4 * 4] =
                        make_float4(dx * inv * lw4.x, dy * inv * lw4.y,
                                    dz * inv * lw4.z, dw * inv * lw4.w);
                }
            }
            __threadfence();          // each thread's global writes visible
            __syncthreads();          // all fences done before flag
            if (tid == 0) atomicAdd(&g_done[it], 1);
        }
        return;
    }

    // =================== consumer ===================
    float* wq   = sm;                 // 64*66
    float* qcur = wq + 64 * 66;       // 1024
    float* qlb  = qcur + 1024;        // 1024
    float* ks   = qlb + 1024;         // 1024 (per-iteration)
    float* vl   = ks + 1024;          // 1024
    float* p    = vl + 1024;          // 256
    float* red  = p + 256;            // 32

    int bb = bx >> 4, h = bx & 15;
    for (int idx = tid; idx < 4096; idx += 256) {
        int j = idx >> 6, d = idx & 63;
        wq[j * 66 + d] = Wlq[idx];
    }
    for (int i = tid; i < 1024; i += 256) {
        int e = i >> 6, d = i & 63;
        qcur[i] = g_q[(size_t)((bb * 16 + e) * 16 + h) * 64 + d];
    }
    int ra = tid & 7;            // rows ra, ra+8
    int c2 = tid >> 3;           // cols 2c2, 2c2+1
    int e_sm = tid >> 4, f_sm = tid & 15;
    int l4 = tid & 15;
    float blq0 = blq[2 * c2], blq1 = blq[2 * c2 + 1];
    float4 lw4 = *(const float4*)&lnc[l4 * 4];
    float temp0 = temp_p[0];
    float ap0 = 0.f, ap1 = 0.f, ap2 = 0.f, ap3 = 0.f;
    __syncthreads();

    for (int it = 0; it < 3; it++) {
        // ---- ql = qcur @ Wlq^T + blq ----
        u64 a00 = 0, a01 = 0, a10 = 0, a11 = 0;
#pragma unroll 8
        for (int dd = 0; dd < 32; dd++) {
            int d = (2 * (dd + tid)) & 62;
            u64 i0 = *(const u64*)&qcur[ra * 64 + d];
            u64 i1 = *(const u64*)&qcur[(ra + 8) * 64 + d];
            u64 w0 = *(const u64*)&wq[(2 * c2) * 66 + d];
            u64 w1 = *(const u64*)&wq[(2 * c2 + 1) * 66 + d];
            ffma2(a00, i0, w0); ffma2(a01, i0, w1);
            ffma2(a10, i1, w0); ffma2(a11, i1, w1);
        }
        __syncthreads();
        {
            float2 f;
            f = *(float2*)&a00; qlb[ra * 64 + 2 * c2]           = f.x + f.y + blq0;
            f = *(float2*)&a01; qlb[ra * 64 + 2 * c2 + 1]       = f.x + f.y + blq1;
            f = *(float2*)&a10; qlb[(ra + 8) * 64 + 2 * c2]     = f.x + f.y + blq0;
            f = *(float2*)&a11; qlb[(ra + 8) * 64 + 2 * c2 + 1] = f.x + f.y + blq1;
        }
        __syncthreads();
        // ---- LN(ql) * tsc * SM_SCALE ----
        float t_it = temp0 + 0.005f * (float)it;
        float tsc = ((t_it != 1.0f) && (t_it > 0.f)) ? rsqrtf(t_it) : 1.0f;
        float sc = tsc * SM_SCALE;
        {
            int rr = tid >> 4;
            float4 v = *(float4*)&qlb[rr * 64 + l4 * 4];
            float s = v.x + v.y + v.z + v.w;
#pragma unroll
            for (int o = 8; o > 0; o >>= 1)
                s += __shfl_xor_sync(0xffffffffu, s, o, 16);
            float mean = s * (1.f / 64.f);
            float dx = v.x - mean, dy = v.y - mean;
            float dz = v.z - mean, dw = v.w - mean;
            float sq = dx * dx + dy * dy + dz * dz + dw * dw;
#pragma unroll
            for (int o = 8; o > 0; o >>= 1)
                sq += __shfl_xor_sync(0xffffffffu, sq, o, 16);
            float inv = rsqrtf(sq * (1.f / 64.f) + 1e-5f) * sc;
            *(float4*)&qlb[rr * 64 + l4 * 4] =
                make_float4(dx * inv * lw4.x, dy * inv * lw4.y,
                            dz * inv * lw4.z, dw * inv * lw4.w);
        }
        // ---- wait for producers, pull ks/vl for this iteration ----
        if (tid == 0) { while (ld_acquire(&g_done[it]) < 64) {} }
        __syncthreads();
        for (int i = tid; i < 1024; i += 256) {
            int e = i >> 6, d = i & 63;
            size_t off = (size_t)it * 65536 +
                         (size_t)((bb * 16 + e) * 16 + h) * 64 + d;
            ks[i] = g_ks[off];
            vl[i] = g_vl[off];
        }
        __syncthreads();
        // ---- logits + parallel softmax ----
        {
            u64 acc0 = 0, acc1 = 0;
#pragma unroll 8
            for (int dd = 0; dd < 32; dd += 2) {
                int d0 = (2 * (dd + tid)) & 62;
                int d1 = (2 * (dd + 1 + tid)) & 62;
                ffma2(acc0, *(const u64*)&qlb[e_sm * 64 + d0],
                            *(const u64*)&ks[f_sm * 64 + d0]);
                ffma2(acc1, *(const u64*)&qlb[e_sm * 64 + d1],
                            *(const u64*)&ks[f_sm * 64 + d1]);
            }
            float2 f0 = *(float2*)&acc0, f1 = *(float2*)&acc1;
            float lg = f0.x + f0.y + f1.x + f1.y;
            float mx = lg;
#pragma unroll
            for (int o = 8; o > 0; o >>= 1)
                mx = fmaxf(mx, __shfl_xor_sync(0xffffffffu, mx, o, 16));
            float ex = __expf(lg - mx);
            float s = ex;
#pragma unroll
            for (int o = 8; o > 0; o >>= 1)
                s += __shfl_xor_sync(0xffffffffu, s, o, 16);
            p[tid] = __fdividef(ex, s);
        }
        __syncthreads();
        // ---- ai = softmax @ vl ; bookkeeping ----
        {
            float b00 = 0, b01 = 0, b10 = 0, b11 = 0;
#pragma unroll
            for (int f = 0; f < 16; f++) {
                float p0 = p[ra * 16 + f];
                float p1 = p[(ra + 8) * 16 + f];
                float2 vv = *(const float2*)&vl[f * 64 + 2 * c2];
                b00 = fmaf(p0, vv.x, b00); b01 = fmaf(p0, vv.y, b01);
                b10 = fmaf(p1, vv.x, b10); b11 = fmaf(p1, vv.y, b11);
            }
            if (it == 0) { ap0 = b00; ap1 = b01; ap2 = b10; ap3 = b11; }
            if (it >= 1) {
                float* dst = (it == 1) ? g_ai1 : g_ai2;
                size_t g0 = (size_t)((bb * 16 + ra) * 16 + h) * 64 + 2 * c2;
                size_t g1 = (size_t)((bb * 16 + ra + 8) * 16 + h) * 64 + 2 * c2;
                *(float2*)&dst[g0] = make_float2(b00, b01);
                *(float2*)&dst[g1] = make_float2(b10, b11);
            }
            qcur[ra * 64 + 2 * c2]           += b00;
            qcur[ra * 64 + 2 * c2 + 1]       += b01;
            qcur[(ra + 8) * 64 + 2 * c2]     += b10;
            qcur[(ra + 8) * 64 + 2 * c2 + 1] += b11;
            if (it == 1) {
                float ds = fabsf(b00 - ap0) + fabsf(b01 - ap1) +
                           fabsf(b10 - ap2) + fabsf(b11 - ap3);
                float tot = blockReduce256(ds, red);
                if (tid == 0) atomicAdd(&g_diffsum, tot);
            }
        }
        __syncthreads();
    }
}
#define KMID_SMEM ((64 * 66 + 4 * 1024 + 256 + 32) * 4)   // 34432 B (consumer max)

// ======================= K4: select ai, Wo proj, red.v4 into out ==========
__global__ __launch_bounds__(128) void k_out(
    const float* __restrict__ Wo, const float* __restrict__ thrp,
    const float* __restrict__ facp, float* __restrict__ out) {
    extern __shared__ float sh[];
    float* sA = sh;
    float* sW = sh + 64 * TK;
    float diff1 = g_diffsum * (1.0f / 8388608.0f);  // mean over B*H*T*hd
    const float* A = (diff1 < thrp[0] + facp[0] * diff1) ? g_ai1 : g_ai2;
    int j0 = blockIdx.x * 128;
    int kb = blockIdx.y * TK;
    u64 acc[64] = {};
    stage_tile(A, Wo, j0, kb, sA, sW);
    cp_wait0();
    __syncthreads();
    int tid = threadIdx.x, rg = tid & 7, cg = tid >> 3;
    compute_tile(sA, sW, acc, rg, cg);
    int c0 = j0 + cg * 8;
#pragma unroll
    for (int i = 0; i < 8; i++) {
        int row = rg * 8 + i;
        int b = row >> 4, t = row & 15;
        float v[8];
#pragma unroll
        for (int j = 0; j < 8; j++) {
            float2 f = *(float2*)&acc[i * 8 + j];
            v[j] = f.x + f.y;
        }
        float* p = &out[((size_t)(b * Tn + t)) * Dn + c0];
        red4(p, v[0], v[1], v[2], v[3]);
        red4(p + 4, v[4], v[5], v[6], v[7]);
    }
}

// ======================= launch ===========================================
extern "C" void kernel_launch(void* const* d_in, const int* in_sizes, int n_in,
                              void* d_out, int out_size) {
    (void)in_sizes; (void)n_in; (void)out_size;
    const float* x    = (const float*)d_in[0];
    const float* Wq   = (const float*)d_in[1];
    const float* bq   = (const float*)d_in[2];
    const float* Wk   = (const float*)d_in[3];
    const float* Wv   = (const float*)d_in[4];
    const float* bv   = (const float*)d_in[5];
    const float* Wo   = (const float*)d_in[6];
    const float* bo   = (const float*)d_in[7];
    const float* lna  = (const float*)d_in[8];
    const float* lnc  = (const float*)d_in[9];
    const float* lnd  = (const float*)d_in[10];
    const float* Wlq  = (const float*)d_in[11];
    const float* blq  = (const float*)d_in[12];
    const float* Wlk  = (const float*)d_in[13];
    const float* blk  = (const float*)d_in[14];
    const float* Wlv  = (const float*)d_in[15];
    const float* blv  = (const float*)d_in[16];
    const float* temp = (const float*)d_in[17];
    const float* thr  = (const float*)d_in[18];
    const float* fac  = (const float*)d_in[19];
    float* out = (float*)d_out;

    static cudaStream_t s2 = nullptr;
    static cudaEvent_t evF = nullptr, evJ = nullptr;
    static bool attrs_set = false;
    if (s2 == nullptr) {
        cudaStreamCreateWithFlags(&s2, cudaStreamNonBlocking);
        cudaEventCreateWithFlags(&evF, cudaEventDisableTiming);
        cudaEventCreateWithFlags(&evJ, cudaEventDisableTiming);
    }
    if (!attrs_set) {
        cudaFuncSetAttribute(k_qkv, cudaFuncAttributeMaxDynamicSharedMemorySize, GEMM_SMEM);
        cudaFuncSetAttribute(k_out, cudaFuncAttributeMaxDynamicSharedMemorySize, GEMM_SMEM);
        cudaFuncSetAttribute(k_mid, cudaFuncAttributeMaxDynamicSharedMemorySize, KMID_SMEM);
        attrs_set = true;
    }

    // fork: bo-fill runs concurrently on s2
    cudaEventRecord(evF, 0);
    cudaStreamWaitEvent(s2, evF, 0);
    k_fill<<<1024, 256, 0, s2>>>(bo, out);

    // main chain on stream 0
    k_ln<<<128, 256>>>(x, lna, bq, bv);
    k_qkv<<<dim3(8, 16, 3), 128, GEMM_SMEM>>>(Wq, Wk, Wv);
    k_mid<<<128, 256, KMID_SMEM>>>(Wlq, blq, Wlk, blk, Wlv, blv, lnc, lnd, temp);

    // join fill before final projection (which red.adds into out)
    cudaEventRecord(evJ, s2);
    cudaStreamWaitEvent(0, evJ, 0);
    k_out<<<dim3(8, 16), 128, GEMM_SMEM>>>(Wo, thr, fac, out);
}